// round 2
// baseline (speedup 1.0000x reference)
#include <cuda_runtime.h>
#include <cuda_bf16.h>

// Problem constants (from reference): X=Y=Z=300, C=16, N=1048576
#define DIM  300
#define HW   (DIM * DIM)
#define CCH  16
#define NGRP 4   // 16 channels / float4

// Channel-last scratch: planes (H, W, C) and lines (L, C).
// float4 arrays guarantee 16B alignment. 17.3 MB total -> L2-resident (126 MB L2).
__device__ float4 g_planeT[3 * HW * NGRP];
__device__ float4 g_lineT [3 * DIM * NGRP];

// ---------------------------------------------------------------------------
// Transpose (C,H,W) -> (H,W,C) via shared-memory tile.
// grid.y = 0..2 : planes; grid.y = 3 : all three lines (tiny).
// Block: 512 threads handles 32 hw-positions x 16 channels.
// ---------------------------------------------------------------------------
__global__ void transpose_all(const float* __restrict__ pxy,
                              const float* __restrict__ pyz,
                              const float* __restrict__ pxz,
                              const float* __restrict__ lx,
                              const float* __restrict__ ly,
                              const float* __restrict__ lz)
{
    const int p = blockIdx.y;
    if (p == 3) {
        // lines: 3 * 300 * 16 = 14400 elements; only blockIdx.x == 0 works.
        if (blockIdx.x != 0) return;
        for (int idx = threadIdx.x; idx < 3 * DIM * CCH; idx += blockDim.x) {
            int q = idx / (DIM * CCH);
            int r = idx - q * (DIM * CCH);
            int i = r >> 4;
            int c = r & 15;
            const float* in = (q == 0) ? lx : (q == 1) ? ly : lz;
            reinterpret_cast<float*>(g_lineT)[idx] = in[c * DIM + i];
        }
        return;
    }

    __shared__ float s[32][17];  // +1 pad: conflict-free both phases
    const float* in = (p == 0) ? pxy : (p == 1) ? pyz : pxz;

    const int hw0 = blockIdx.x * 32;
    const int tid = threadIdx.x;

    int c = tid >> 5, j = tid & 31;          // load: consecutive tid = consecutive hw
    int hw = hw0 + j;
    if (hw < HW) s[j][c] = in[c * HW + hw];
    __syncthreads();

    int j2 = tid >> 4, c2 = tid & 15;        // store: consecutive tid = consecutive out
    int hw2 = hw0 + j2;
    if (hw2 < HW)
        reinterpret_cast<float*>(g_planeT)[(size_t)(p * HW + hw2) * CCH + c2] = s[j2][c2];
}

// ---------------------------------------------------------------------------
// Sampling helpers
// ---------------------------------------------------------------------------
struct BilinIdx {
    int i00, i01, i10, i11;
    float w00, w01, w10, w11;
};

__device__ __forceinline__ BilinIdx bilin_setup(float2 c)
{
    float ix = (c.x + 1.0f) * 0.5f * (DIM - 1);
    float iy = (c.y + 1.0f) * 0.5f * (DIM - 1);
    float ix0f = floorf(ix);
    float iy0f = floorf(iy);
    float wx = ix - ix0f;
    float wy = iy - iy0f;
    int ix0 = min(max((int)ix0f, 0), DIM - 1);
    int ix1 = min(ix0 + 1, DIM - 1);
    int iy0 = min(max((int)iy0f, 0), DIM - 1);
    int iy1 = min(iy0 + 1, DIM - 1);
    BilinIdx b;
    b.i00 = iy0 * DIM + ix0;
    b.i01 = iy0 * DIM + ix1;
    b.i10 = iy1 * DIM + ix0;
    b.i11 = iy1 * DIM + ix1;
    b.w00 = (1.0f - wx) * (1.0f - wy);
    b.w01 = wx * (1.0f - wy);
    b.w10 = (1.0f - wx) * wy;
    b.w11 = wx * wy;
    return b;
}

struct LineIdx {
    int i0, i1;
    float w;
};

__device__ __forceinline__ LineIdx line_setup(float t)
{
    float iy = (t + 1.0f) * 0.5f * (DIM - 1);
    float f = floorf(iy);
    LineIdx L;
    L.w = iy - f;
    L.i0 = min(max((int)f, 0), DIM - 1);
    L.i1 = min(L.i0 + 1, DIM - 1);
    return L;
}

__device__ __forceinline__ float4 combine(float4 v00, float4 v01, float4 v10,
                                          float4 v11, const BilinIdx& b,
                                          float4 a, float4 bb, float lw)
{
    float4 fp, fl, r;
    fp.x = v00.x * b.w00 + v01.x * b.w01 + v10.x * b.w10 + v11.x * b.w11;
    fp.y = v00.y * b.w00 + v01.y * b.w01 + v10.y * b.w10 + v11.y * b.w11;
    fp.z = v00.z * b.w00 + v01.z * b.w01 + v10.z * b.w10 + v11.z * b.w11;
    fp.w = v00.w * b.w00 + v01.w * b.w01 + v10.w * b.w10 + v11.w * b.w11;
    float iw = 1.0f - lw;
    fl.x = a.x * iw + bb.x * lw;
    fl.y = a.y * iw + bb.y * lw;
    fl.z = a.z * iw + bb.z * lw;
    fl.w = a.w * iw + bb.w * lw;
    r.x = fp.x * fl.x; r.y = fp.y * fl.y; r.z = fp.z * fl.z; r.w = fp.w * fl.w;
    return r;
}

// ---------------------------------------------------------------------------
// Main sampling kernel: 4 threads per sample (one float4 channel group each).
// All 18 gather loads are issued before any combine math (max MLP).
// ---------------------------------------------------------------------------
__global__ void __launch_bounds__(256)
sample_kernel(const float* __restrict__ cp,
              const float* __restrict__ cl,
              float* __restrict__ out,
              int Ns)
{
    int tid = blockIdx.x * blockDim.x + threadIdx.x;
    if (tid >= Ns * NGRP) return;
    int n = tid >> 2;
    int g = tid & 3;

    // coords_plane layout: (3, N, 2); coords_line: only component 1 matters (W==1)
    const float2* cp2 = reinterpret_cast<const float2*>(cp);
    const float2* cl2 = reinterpret_cast<const float2*>(cl);
    float2 c_xy = cp2[0 * Ns + n];
    float2 c_yz = cp2[1 * Ns + n];
    float2 c_xz = cp2[2 * Ns + n];
    float  t_x  = cl2[0 * Ns + n].y;
    float  t_y  = cl2[1 * Ns + n].y;
    float  t_z  = cl2[2 * Ns + n].y;

    BilinIdx b_yz = bilin_setup(c_yz);
    BilinIdx b_xz = bilin_setup(c_xz);
    BilinIdx b_xy = bilin_setup(c_xy);
    LineIdx  L_x  = line_setup(t_x);
    LineIdx  L_y  = line_setup(t_y);
    LineIdx  L_z  = line_setup(t_z);

    const float4* p_xy = g_planeT + 0 * HW * NGRP;
    const float4* p_yz = g_planeT + 1 * HW * NGRP;
    const float4* p_xz = g_planeT + 2 * HW * NGRP;
    const float4* l_x  = g_lineT  + 0 * DIM * NGRP;
    const float4* l_y  = g_lineT  + 1 * DIM * NGRP;
    const float4* l_z  = g_lineT  + 2 * DIM * NGRP;

    // ---- issue all loads up front (18 independent 16B loads) ----
    float4 a00 = p_yz[b_yz.i00 * NGRP + g];
    float4 a01 = p_yz[b_yz.i01 * NGRP + g];
    float4 a10 = p_yz[b_yz.i10 * NGRP + g];
    float4 a11 = p_yz[b_yz.i11 * NGRP + g];
    float4 b00 = p_xz[b_xz.i00 * NGRP + g];
    float4 b01 = p_xz[b_xz.i01 * NGRP + g];
    float4 b10 = p_xz[b_xz.i10 * NGRP + g];
    float4 b11 = p_xz[b_xz.i11 * NGRP + g];
    float4 d00 = p_xy[b_xy.i00 * NGRP + g];
    float4 d01 = p_xy[b_xy.i01 * NGRP + g];
    float4 d10 = p_xy[b_xy.i10 * NGRP + g];
    float4 d11 = p_xy[b_xy.i11 * NGRP + g];
    float4 lx0 = l_x[L_x.i0 * NGRP + g];
    float4 lx1 = l_x[L_x.i1 * NGRP + g];
    float4 ly0 = l_y[L_y.i0 * NGRP + g];
    float4 ly1 = l_y[L_y.i1 * NGRP + g];
    float4 lz0 = l_z[L_z.i0 * NGRP + g];
    float4 lz1 = l_z[L_z.i1 * NGRP + g];

    float4* o = reinterpret_cast<float4*>(out);
    // out_x = f_yz * f_x ; out_y = f_xz * f_y ; out_z = f_xy * f_z
    o[(size_t)(0 * Ns + n) * NGRP + g] = combine(a00, a01, a10, a11, b_yz, lx0, lx1, L_x.w);
    o[(size_t)(1 * Ns + n) * NGRP + g] = combine(b00, b01, b10, b11, b_xz, ly0, ly1, L_y.w);
    o[(size_t)(2 * Ns + n) * NGRP + g] = combine(d00, d01, d10, d11, b_xy, lz0, lz1, L_z.w);
}

// ---------------------------------------------------------------------------
// Launch
// ---------------------------------------------------------------------------
extern "C" void kernel_launch(void* const* d_in, const int* in_sizes, int n_in,
                              void* d_out, int out_size)
{
    const float* coords_plane = (const float*)d_in[0];  // (3,1,N,1,2)
    const float* coords_line  = (const float*)d_in[1];  // (3,1,N,1,2)
    const float* plane_xy     = (const float*)d_in[2];  // (1,C,Y,X)
    const float* plane_yz     = (const float*)d_in[3];  // (1,C,Z,Y)
    const float* plane_xz     = (const float*)d_in[4];  // (1,C,Z,X)
    const float* line_x       = (const float*)d_in[5];  // (1,C,X,1)
    const float* line_y       = (const float*)d_in[6];  // (1,C,Y,1)
    const float* line_z       = (const float*)d_in[7];  // (1,C,Z,1)

    const int Ns = in_sizes[0] / 6;  // coords_plane has 3*N*2 elements

    // 1) Reshape planes + lines to channel-last scratch (single kernel)
    {
        dim3 grid((HW + 31) / 32, 4);
        transpose_all<<<grid, 512>>>(plane_xy, plane_yz, plane_xz,
                                     line_x, line_y, line_z);
    }

    // 2) Sample: 4 threads per sample
    {
        long long threads = (long long)Ns * NGRP;
        int block = 256;
        int grid = (int)((threads + block - 1) / block);
        sample_kernel<<<grid, block>>>(coords_plane, coords_line, (float*)d_out, Ns);
    }
}

// round 3
// speedup vs baseline: 1.0354x; 1.0354x over previous
#include <cuda_runtime.h>
#include <cuda_bf16.h>

// Problem constants: X=Y=Z=300, C=16, N=1048576
#define DIM  300
#define HW   (DIM * DIM)
#define CCH  16
#define NGRP 4     // 16 channels / float4
#define TTILE 256  // hw positions per transpose block

// Channel-last scratch: planes (H,W,C), lines (L,C). 17.3 MB -> L2-resident.
__device__ float4 g_planeT[3 * HW * NGRP];
__device__ float4 g_lineT [3 * DIM * NGRP];

// ---------------------------------------------------------------------------
// Transpose (C,H,W) -> (H,W,C).  grid.y = 0..2 planes, 3 = lines.
// Block: 256 threads handle 256 hw-positions x 16 channels (16 KB tile).
// Load: 16 coalesced 1KB sweeps.  Store: float4, perfectly coalesced.
// smem stride 257 -> conflict-free in both phases.
// ---------------------------------------------------------------------------
__global__ void transpose_all(const float* __restrict__ pxy,
                              const float* __restrict__ pyz,
                              const float* __restrict__ pxz,
                              const float* __restrict__ lx,
                              const float* __restrict__ ly,
                              const float* __restrict__ lz)
{
    const int p = blockIdx.y;
    if (p == 3) {
        if (blockIdx.x != 0) return;
        for (int idx = threadIdx.x; idx < 3 * DIM * CCH; idx += blockDim.x) {
            int q = idx / (DIM * CCH);
            int r = idx - q * (DIM * CCH);
            int i = r >> 4;
            int c = r & 15;
            const float* in = (q == 0) ? lx : (q == 1) ? ly : lz;
            reinterpret_cast<float*>(g_lineT)[idx] = in[c * DIM + i];
        }
        return;
    }

    __shared__ float s[CCH * 257];
    const float* in = (p == 0) ? pxy : (p == 1) ? pyz : pxz;
    const int hw0 = blockIdx.x * TTILE;
    const int t   = threadIdx.x;

    #pragma unroll
    for (int c = 0; c < CCH; c++) {
        int hw = hw0 + t;
        if (hw < HW) s[c * 257 + t] = in[c * HW + hw];
    }
    __syncthreads();

    #pragma unroll
    for (int it = 0; it < 4; it++) {
        int idx = it * TTILE + t;          // 0..1023
        int h   = idx >> 2;                // local hw
        int cg  = idx & 3;                 // channel group
        int hw  = hw0 + h;
        if (hw < HW) {
            float4 v = make_float4(s[(cg * 4 + 0) * 257 + h],
                                   s[(cg * 4 + 1) * 257 + h],
                                   s[(cg * 4 + 2) * 257 + h],
                                   s[(cg * 4 + 3) * 257 + h]);
            g_planeT[((size_t)p * HW + hw) * NGRP + cg] = v;
        }
    }
}

// ---------------------------------------------------------------------------
// Sampler: one kernel instantiation per output term.
//   KP: coords_plane row   PIDX: plane index   KL: coords_line row (== LIDX)
//   KO: output row
// 4 threads per sample (one float4 channel group each).
// ---------------------------------------------------------------------------
template <int KP, int PIDX, int KL, int KO>
__global__ void __launch_bounds__(256, 8)
sample_one(const float2* __restrict__ cp2,
           const float2* __restrict__ cl2,
           float4* __restrict__ out4,
           int Ns)
{
    int tid = blockIdx.x * blockDim.x + threadIdx.x;
    if (tid >= Ns * NGRP) return;
    int n = tid >> 2;
    int g = tid & 3;

    float2 c = cp2[(size_t)KP * Ns + n];
    float  t = cl2[(size_t)KL * Ns + n].y;   // W==1 -> only y matters

    // bilinear setup
    float ix = (c.x + 1.0f) * 0.5f * (DIM - 1);
    float iy = (c.y + 1.0f) * 0.5f * (DIM - 1);
    float ix0f = floorf(ix), iy0f = floorf(iy);
    float wx = ix - ix0f,    wy = iy - iy0f;
    int ix0 = min(max((int)ix0f, 0), DIM - 1);
    int ix1 = min(ix0 + 1, DIM - 1);
    int iy0 = min(max((int)iy0f, 0), DIM - 1);
    int iy1 = min(iy0 + 1, DIM - 1);

    // line setup
    float it_ = (t + 1.0f) * 0.5f * (DIM - 1);
    float itf = floorf(it_);
    float lw  = it_ - itf;
    int   li0 = min(max((int)itf, 0), DIM - 1);
    int   li1 = min(li0 + 1, DIM - 1);

    const float4* plane = g_planeT + (size_t)PIDX * HW * NGRP;
    const float4* line  = g_lineT  + (size_t)KL  * DIM * NGRP;

    // issue all 6 independent loads up front
    float4 v00 = plane[((iy0 * DIM + ix0) << 2) + g];
    float4 v01 = plane[((iy0 * DIM + ix1) << 2) + g];
    float4 v10 = plane[((iy1 * DIM + ix0) << 2) + g];
    float4 v11 = plane[((iy1 * DIM + ix1) << 2) + g];
    float4 l0  = line[(li0 << 2) + g];
    float4 l1  = line[(li1 << 2) + g];

    float w00 = (1.0f - wx) * (1.0f - wy);
    float w01 = wx * (1.0f - wy);
    float w10 = (1.0f - wx) * wy;
    float w11 = wx * wy;
    float liw = 1.0f - lw;

    float4 r;
    r.x = (v00.x * w00 + v01.x * w01 + v10.x * w10 + v11.x * w11) * (l0.x * liw + l1.x * lw);
    r.y = (v00.y * w00 + v01.y * w01 + v10.y * w10 + v11.y * w11) * (l0.y * liw + l1.y * lw);
    r.z = (v00.z * w00 + v01.z * w01 + v10.z * w10 + v11.z * w11) * (l0.z * liw + l1.z * lw);
    r.w = (v00.w * w00 + v01.w * w01 + v10.w * w10 + v11.w * w11) * (l0.w * liw + l1.w * lw);

    out4[((size_t)KO * Ns + n) * NGRP + g] = r;
}

// ---------------------------------------------------------------------------
// Launch
// ---------------------------------------------------------------------------
extern "C" void kernel_launch(void* const* d_in, const int* in_sizes, int n_in,
                              void* d_out, int out_size)
{
    const float* coords_plane = (const float*)d_in[0];  // (3,N,2)
    const float* coords_line  = (const float*)d_in[1];  // (3,N,2)
    const float* plane_xy     = (const float*)d_in[2];
    const float* plane_yz     = (const float*)d_in[3];
    const float* plane_xz     = (const float*)d_in[4];
    const float* line_x       = (const float*)d_in[5];
    const float* line_y       = (const float*)d_in[6];
    const float* line_z       = (const float*)d_in[7];

    const int Ns = in_sizes[0] / 6;

    {
        dim3 grid((HW + TTILE - 1) / TTILE, 4);
        transpose_all<<<grid, TTILE>>>(plane_xy, plane_yz, plane_xz,
                                       line_x, line_y, line_z);
    }

    const float2* cp2 = (const float2*)coords_plane;
    const float2* cl2 = (const float2*)coords_line;
    float4* out4 = (float4*)d_out;

    int threads = Ns * NGRP;
    int block = 256;
    int grid = (threads + block - 1) / block;

    // out_x = f(plane_yz, cp[1]) * f(line_x, cl[0])
    sample_one<1, 1, 0, 0><<<grid, block>>>(cp2, cl2, out4, Ns);
    // out_y = f(plane_xz, cp[2]) * f(line_y, cl[1])
    sample_one<2, 2, 1, 1><<<grid, block>>>(cp2, cl2, out4, Ns);
    // out_z = f(plane_xy, cp[0]) * f(line_z, cl[2])
    sample_one<0, 0, 2, 2><<<grid, block>>>(cp2, cl2, out4, Ns);
}

// round 4
// speedup vs baseline: 1.1968x; 1.1558x over previous
#include <cuda_runtime.h>
#include <cuda_bf16.h>

// Problem constants: X=Y=Z=300, C=16, N=1048576
#define DIM   300
#define HW    (DIM * DIM)
#define CCH   16
#define NGRP  4                       // 16 channels / float4
#define PLANE_F4   (3 * HW * NGRP)    // 1,080,000 float4 outputs
#define LINE_F4    (3 * DIM * NGRP)   // 3,600 float4 outputs
#define TOTAL_F4   (PLANE_F4 + LINE_F4)

// Channel-last scratch: planes (H,W,C), lines (L,C). 17.3 MB -> L2-resident.
__device__ float4 g_planeT[PLANE_F4];
__device__ float4 g_lineT [LINE_F4];

// ---------------------------------------------------------------------------
// Transpose (C,H,W) -> (H,W,C) as a pure gather: one thread per output float4.
// Stores are perfectly coalesced (consecutive tid -> consecutive 16B).
// Loads: per warp, each of the 4 k-loads touches 4 channel-planes x 32B
// contiguous runs -> sector-efficient. No smem, no syncs, max occupancy.
// ---------------------------------------------------------------------------
__global__ void __launch_bounds__(256)
transpose_all(const float* __restrict__ pxy,
              const float* __restrict__ pyz,
              const float* __restrict__ pxz,
              const float* __restrict__ lx,
              const float* __restrict__ ly,
              const float* __restrict__ lz)
{
    int idx = blockIdx.x * blockDim.x + threadIdx.x;
    if (idx >= TOTAL_F4) return;

    if (idx < PLANE_F4) {
        int p   = idx / (HW * NGRP);
        int r   = idx - p * (HW * NGRP);
        int hw  = r >> 2;
        int cg  = r & 3;
        const float* in = (p == 0) ? pxy : (p == 1) ? pyz : pxz;
        float4 v;
        v.x = in[(cg * 4 + 0) * HW + hw];
        v.y = in[(cg * 4 + 1) * HW + hw];
        v.z = in[(cg * 4 + 2) * HW + hw];
        v.w = in[(cg * 4 + 3) * HW + hw];
        g_planeT[idx] = v;
    } else {
        int r2  = idx - PLANE_F4;           // 0 .. 3599
        int q   = r2 / (DIM * NGRP);
        int r   = r2 - q * (DIM * NGRP);
        int i   = r >> 2;
        int cg  = r & 3;
        const float* in = (q == 0) ? lx : (q == 1) ? ly : lz;
        float4 v;
        v.x = in[(cg * 4 + 0) * DIM + i];
        v.y = in[(cg * 4 + 1) * DIM + i];
        v.z = in[(cg * 4 + 2) * DIM + i];
        v.w = in[(cg * 4 + 3) * DIM + i];
        g_lineT[r2] = v;
    }
}

// ---------------------------------------------------------------------------
// Sampler: one kernel instantiation per output term, persistent grid-stride.
// The term's line table (300 x 16 floats = 19.2 KB) lives in shared memory,
// removing 16 of ~55 L1 wavefronts per warp from the LDG path.
//   KP: coords_plane row   PIDX: plane index   KL: coords_line row / line idx
//   KO: output row
// 4 threads per sample (one float4 channel group each).
// ---------------------------------------------------------------------------
template <int KP, int PIDX, int KL, int KO>
__global__ void __launch_bounds__(256, 8)
sample_one(const float2* __restrict__ cp2,
           const float2* __restrict__ cl2,
           float4* __restrict__ out4,
           int Ns)
{
    __shared__ float4 sline[DIM * NGRP];   // 19.2 KB
    for (int i = threadIdx.x; i < DIM * NGRP; i += blockDim.x)
        sline[i] = g_lineT[KL * DIM * NGRP + i];
    __syncthreads();

    const float4* plane = g_planeT + (size_t)PIDX * HW * NGRP;
    const int total = Ns * NGRP;
    const int stride = gridDim.x * blockDim.x;

    for (int tid = blockIdx.x * blockDim.x + threadIdx.x; tid < total;
         tid += stride) {
        int n = tid >> 2;
        int g = tid & 3;

        float2 c = cp2[(size_t)KP * Ns + n];
        float  t = cl2[(size_t)KL * Ns + n].y;   // W==1 -> only y matters

        // bilinear setup
        float ix = (c.x + 1.0f) * 0.5f * (DIM - 1);
        float iy = (c.y + 1.0f) * 0.5f * (DIM - 1);
        float ix0f = floorf(ix), iy0f = floorf(iy);
        float wx = ix - ix0f,    wy = iy - iy0f;
        int ix0 = min(max((int)ix0f, 0), DIM - 1);
        int ix1 = min(ix0 + 1, DIM - 1);
        int iy0 = min(max((int)iy0f, 0), DIM - 1);
        int iy1 = min(iy0 + 1, DIM - 1);

        // line setup
        float it_ = (t + 1.0f) * 0.5f * (DIM - 1);
        float itf = floorf(it_);
        float lw  = it_ - itf;
        int   li0 = min(max((int)itf, 0), DIM - 1);
        int   li1 = min(li0 + 1, DIM - 1);

        // issue plane gathers up front (4 independent 16B loads)
        float4 v00 = plane[((iy0 * DIM + ix0) << 2) + g];
        float4 v01 = plane[((iy0 * DIM + ix1) << 2) + g];
        float4 v10 = plane[((iy1 * DIM + ix0) << 2) + g];
        float4 v11 = plane[((iy1 * DIM + ix1) << 2) + g];
        float4 l0  = sline[(li0 << 2) + g];
        float4 l1  = sline[(li1 << 2) + g];

        float w00 = (1.0f - wx) * (1.0f - wy);
        float w01 = wx * (1.0f - wy);
        float w10 = (1.0f - wx) * wy;
        float w11 = wx * wy;
        float liw = 1.0f - lw;

        float4 r;
        r.x = (v00.x * w00 + v01.x * w01 + v10.x * w10 + v11.x * w11) *
              (l0.x * liw + l1.x * lw);
        r.y = (v00.y * w00 + v01.y * w01 + v10.y * w10 + v11.y * w11) *
              (l0.y * liw + l1.y * lw);
        r.z = (v00.z * w00 + v01.z * w01 + v10.z * w10 + v11.z * w11) *
              (l0.z * liw + l1.z * lw);
        r.w = (v00.w * w00 + v01.w * w01 + v10.w * w10 + v11.w * w11) *
              (l0.w * liw + l1.w * lw);

        out4[((size_t)KO * Ns + n) * NGRP + g] = r;
    }
}

// ---------------------------------------------------------------------------
// Launch
// ---------------------------------------------------------------------------
extern "C" void kernel_launch(void* const* d_in, const int* in_sizes, int n_in,
                              void* d_out, int out_size)
{
    const float* coords_plane = (const float*)d_in[0];  // (3,N,2)
    const float* coords_line  = (const float*)d_in[1];  // (3,N,2)
    const float* plane_xy     = (const float*)d_in[2];
    const float* plane_yz     = (const float*)d_in[3];
    const float* plane_xz     = (const float*)d_in[4];
    const float* line_x       = (const float*)d_in[5];
    const float* line_y       = (const float*)d_in[6];
    const float* line_z       = (const float*)d_in[7];

    const int Ns = in_sizes[0] / 6;

    transpose_all<<<(TOTAL_F4 + 255) / 256, 256>>>(plane_xy, plane_yz, plane_xz,
                                                   line_x, line_y, line_z);

    const float2* cp2 = (const float2*)coords_plane;
    const float2* cl2 = (const float2*)coords_line;
    float4* out4 = (float4*)d_out;

    // persistent grid: 148 SMs x 8 blocks of 256 threads = one full wave
    const int grid = 148 * 8;
    const int block = 256;

    // out_x = f(plane_yz, cp[1]) * f(line_x, cl[0])
    sample_one<1, 1, 0, 0><<<grid, block>>>(cp2, cl2, out4, Ns);
    // out_y = f(plane_xz, cp[2]) * f(line_y, cl[1])
    sample_one<2, 2, 1, 1><<<grid, block>>>(cp2, cl2, out4, Ns);
    // out_z = f(plane_xy, cp[0]) * f(line_z, cl[2])
    sample_one<0, 0, 2, 2><<<grid, block>>>(cp2, cl2, out4, Ns);
}